// round 1
// baseline (speedup 1.0000x reference)
#include <cuda_runtime.h>
#include <stdint.h>

#define LUT_DIM 33
#define NPAIR (33 * 33 * 32)          // pairs along r
#define CH_STRIDE (33 * 33 * 33)      // per-channel LUT stride (floats)
#define HW (1080 * 1920)              // pixels per plane
#define HW4 (HW / 4)                  // float4 groups per plane
#define NBATCH 4

// Repacked LUT: for each (b, g, r) with r in [0,32), an aligned 32-byte block:
//   [ L0[b][g][r], L1[b][g][r], L2[b][g][r], pad,
//     L0[b][g][r+1], L1[b][g][r+1], L2[b][g][r+1], pad ]
// Every (dg, db) corner-pair fetch is then exactly ONE aligned 32B L2 sector.
__device__ __align__(32) float g_pairs[NPAIR * 8];

__global__ void pack_lut_kernel(const float* __restrict__ LUT) {
    int i = blockIdx.x * blockDim.x + threadIdx.x;
    if (i >= NPAIR) return;
    int r = i & 31;
    int t = i >> 5;          // b*33 + g
    int g = t % 33;
    int b = t / 33;
    int base = (b * 33 + g) * 33 + r;   // index into one channel plane of LUT
    float4 lo = make_float4(LUT[base],
                            LUT[base + CH_STRIDE],
                            LUT[base + 2 * CH_STRIDE], 0.0f);
    float4 hi = make_float4(LUT[base + 1],
                            LUT[base + 1 + CH_STRIDE],
                            LUT[base + 1 + 2 * CH_STRIDE], 0.0f);
    float4* dst = reinterpret_cast<float4*>(g_pairs) + i * 2;
    dst[0] = lo;
    dst[1] = hi;
}

struct F3 { float x, y, z; };

__device__ __forceinline__ F3 lut_interp(float r, float g, float b) {
    // scaled = clamp(v,0,1) * 32 ; idx = min(floor(scaled), 31); frac = scaled - idx
    float sr = __saturatef(r) * 32.0f;
    float sg = __saturatef(g) * 32.0f;
    float sb = __saturatef(b) * 32.0f;
    int ri = min((int)sr, 31);
    int gi = min((int)sg, 31);
    int bi = min((int)sb, 31);
    float fr = sr - (float)ri;
    float fg = sg - (float)gi;
    float fb = sb - (float)bi;

    const float4* __restrict__ P = reinterpret_cast<const float4*>(g_pairs);
    // pair index (b,g,r) -> ((b*33+g)*32 + r); each pair = 2 float4
    int q = (((bi * 33 + gi) << 5) + ri) << 1;
    const int DG = 32 * 2;        // +1 in g: 32 pairs ahead (in float4 units)
    const int DB = 33 * 32 * 2;   // +1 in b

    float4 a0 = __ldg(P + q);            float4 a1 = __ldg(P + q + 1);        // (dg=0,db=0)
    float4 b0 = __ldg(P + q + DG);       float4 b1 = __ldg(P + q + DG + 1);   // (dg=1,db=0)
    float4 c0 = __ldg(P + q + DB);       float4 c1 = __ldg(P + q + DB + 1);   // (dg=0,db=1)
    float4 d0 = __ldg(P + q + DB + DG);  float4 d1 = __ldg(P + q + DB + DG + 1);

    // lerp along r for each of the 4 (dg,db) pairs
    F3 va = { fmaf(fr, a1.x - a0.x, a0.x), fmaf(fr, a1.y - a0.y, a0.y), fmaf(fr, a1.z - a0.z, a0.z) };
    F3 vb = { fmaf(fr, b1.x - b0.x, b0.x), fmaf(fr, b1.y - b0.y, b0.y), fmaf(fr, b1.z - b0.z, b0.z) };
    F3 vc = { fmaf(fr, c1.x - c0.x, c0.x), fmaf(fr, c1.y - c0.y, c0.y), fmaf(fr, c1.z - c0.z, c0.z) };
    F3 vd = { fmaf(fr, d1.x - d0.x, d0.x), fmaf(fr, d1.y - d0.y, d0.y), fmaf(fr, d1.z - d0.z, d0.z) };

    // lerp along g
    F3 v0 = { fmaf(fg, vb.x - va.x, va.x), fmaf(fg, vb.y - va.y, va.y), fmaf(fg, vb.z - va.z, va.z) };
    F3 v1 = { fmaf(fg, vd.x - vc.x, vc.x), fmaf(fg, vd.y - vc.y, vc.y), fmaf(fg, vd.z - vc.z, vc.z) };

    // lerp along b
    F3 o = { fmaf(fb, v1.x - v0.x, v0.x), fmaf(fb, v1.y - v0.y, v0.y), fmaf(fb, v1.z - v0.z, v0.z) };
    return o;
}

__global__ void __launch_bounds__(256)
lut_apply_kernel(const float* __restrict__ x, float* __restrict__ out) {
    int tid = blockIdx.x * blockDim.x + threadIdx.x;
    if (tid >= NBATCH * HW4) return;
    int b = tid / HW4;
    int j = tid - b * HW4;

    const float4* xp = reinterpret_cast<const float4*>(x) + (size_t)b * 3 * HW4;
    float4* op = reinterpret_cast<float4*>(out) + (size_t)b * 3 * HW4;

    float4 r4 = __ldg(xp + j);
    float4 g4 = __ldg(xp + j + HW4);
    float4 b4 = __ldg(xp + j + 2 * HW4);

    float rs[4] = { r4.x, r4.y, r4.z, r4.w };
    float gs[4] = { g4.x, g4.y, g4.z, g4.w };
    float bs[4] = { b4.x, b4.y, b4.z, b4.w };
    float o0[4], o1[4], o2[4];

#pragma unroll
    for (int i = 0; i < 4; i++) {
        F3 v = lut_interp(rs[i], gs[i], bs[i]);
        o0[i] = v.x; o1[i] = v.y; o2[i] = v.z;
    }

    op[j]           = make_float4(o0[0], o0[1], o0[2], o0[3]);
    op[j + HW4]     = make_float4(o1[0], o1[1], o1[2], o1[3]);
    op[j + 2 * HW4] = make_float4(o2[0], o2[1], o2[2], o2[3]);
}

extern "C" void kernel_launch(void* const* d_in, const int* in_sizes, int n_in,
                              void* d_out, int out_size) {
    const float* x   = (const float*)d_in[0];   // (4,3,1080,1920) fp32
    const float* LUT = (const float*)d_in[1];   // (3,33,33,33) fp32
    float* out = (float*)d_out;

    pack_lut_kernel<<<(NPAIR + 255) / 256, 256>>>(LUT);

    int total = NBATCH * HW4;                   // 2,073,600 threads
    lut_apply_kernel<<<(total + 255) / 256, 256>>>(x, out);
}

// round 2
// speedup vs baseline: 1.5684x; 1.5684x over previous
#include <cuda_runtime.h>
#include <cuda_fp16.h>
#include <stdint.h>

#define LUT_DIM 33
#define NPAIR (33 * 33 * 32)          // (b,g) cells * 32 r-pairs
#define CH_STRIDE (33 * 33 * 33)      // per-channel stride in source LUT (floats)
#define HW (1080 * 1920)              // pixels per plane
#define HW4 (HW / 4)                  // float4 groups per plane
#define NBATCH 4

// Repacked fp16 LUT: for each (b, g, r) with r in [0,32), ONE 16-byte block:
//   [ c0@r, c1@r, c2@r, pad, c0@r+1, c1@r+1, c2@r+1, pad ]   (8 halves)
// One LDG.128 per (dg,db) corner-pair -> 4 divergent loads per pixel total.
__device__ __align__(16) __half g_pairs_h[NPAIR * 8];

__global__ void pack_lut_kernel(const float* __restrict__ LUT) {
    int i = blockIdx.x * blockDim.x + threadIdx.x;
    if (i >= NPAIR) return;
    int r = i & 31;
    int t = i >> 5;          // b*33 + g
    int g = t % 33;
    int b = t / 33;
    int base = (b * 33 + g) * 33 + r;
    __half blk[8];
    blk[0] = __float2half_rn(LUT[base]);
    blk[1] = __float2half_rn(LUT[base + CH_STRIDE]);
    blk[2] = __float2half_rn(LUT[base + 2 * CH_STRIDE]);
    blk[3] = __ushort_as_half(0);
    blk[4] = __float2half_rn(LUT[base + 1]);
    blk[5] = __float2half_rn(LUT[base + 1 + CH_STRIDE]);
    blk[6] = __float2half_rn(LUT[base + 1 + 2 * CH_STRIDE]);
    blk[7] = __ushort_as_half(0);
    reinterpret_cast<uint4*>(g_pairs_h)[i] = *reinterpret_cast<const uint4*>(blk);
}

struct F3 { float x, y, z; };

__device__ __forceinline__ float2 h2f(unsigned u) {
    __half2 h = *reinterpret_cast<__half2*>(&u);
    return __half22float2(h);
}

// One 16B block -> lerp along r for 3 channels.
__device__ __forceinline__ F3 lerp_r(uint4 v, float fr) {
    float2 lo01 = h2f(v.x);   // c0@r, c1@r
    float2 lo2_ = h2f(v.y);   // c2@r, pad
    float2 hi01 = h2f(v.z);   // c0@r+1, c1@r+1
    float2 hi2_ = h2f(v.w);   // c2@r+1, pad
    F3 o;
    o.x = fmaf(fr, hi01.x - lo01.x, lo01.x);
    o.y = fmaf(fr, hi01.y - lo01.y, lo01.y);
    o.z = fmaf(fr, hi2_.x - lo2_.x, lo2_.x);
    return o;
}

__device__ __forceinline__ F3 lut_interp(float r, float g, float b) {
    float sr = __saturatef(r) * 32.0f;
    float sg = __saturatef(g) * 32.0f;
    float sb = __saturatef(b) * 32.0f;
    int ri = min((int)sr, 31);
    int gi = min((int)sg, 31);
    int bi = min((int)sb, 31);
    float fr = sr - (float)ri;
    float fg = sg - (float)gi;
    float fb = sb - (float)bi;

    const uint4* __restrict__ P = reinterpret_cast<const uint4*>(g_pairs_h);
    int q = ((bi * 33 + gi) << 5) + ri;   // block index
    const int DG = 32;        // +1 in g
    const int DB = 33 * 32;   // +1 in b

    uint4 A = __ldg(P + q);             // (dg=0, db=0)
    uint4 B = __ldg(P + q + DG);        // (dg=1, db=0)
    uint4 C = __ldg(P + q + DB);        // (dg=0, db=1)
    uint4 D = __ldg(P + q + DB + DG);   // (dg=1, db=1)

    F3 va = lerp_r(A, fr);
    F3 vb = lerp_r(B, fr);
    F3 vc = lerp_r(C, fr);
    F3 vd = lerp_r(D, fr);

    // lerp along g
    F3 v0 = { fmaf(fg, vb.x - va.x, va.x), fmaf(fg, vb.y - va.y, va.y), fmaf(fg, vb.z - va.z, va.z) };
    F3 v1 = { fmaf(fg, vd.x - vc.x, vc.x), fmaf(fg, vd.y - vc.y, vc.y), fmaf(fg, vd.z - vc.z, vc.z) };

    // lerp along b
    F3 o = { fmaf(fb, v1.x - v0.x, v0.x), fmaf(fb, v1.y - v0.y, v0.y), fmaf(fb, v1.z - v0.z, v0.z) };
    return o;
}

__global__ void __launch_bounds__(256)
lut_apply_kernel(const float* __restrict__ x, float* __restrict__ out) {
    int tid = blockIdx.x * blockDim.x + threadIdx.x;
    if (tid >= NBATCH * HW4) return;
    int b = tid / HW4;
    int j = tid - b * HW4;

    const float4* xp = reinterpret_cast<const float4*>(x) + (size_t)b * 3 * HW4;
    float4* op = reinterpret_cast<float4*>(out) + (size_t)b * 3 * HW4;

    float4 r4 = __ldg(xp + j);
    float4 g4 = __ldg(xp + j + HW4);
    float4 b4 = __ldg(xp + j + 2 * HW4);

    float rs[4] = { r4.x, r4.y, r4.z, r4.w };
    float gs[4] = { g4.x, g4.y, g4.z, g4.w };
    float bs[4] = { b4.x, b4.y, b4.z, b4.w };
    float o0[4], o1[4], o2[4];

#pragma unroll
    for (int i = 0; i < 4; i++) {
        F3 v = lut_interp(rs[i], gs[i], bs[i]);
        o0[i] = v.x; o1[i] = v.y; o2[i] = v.z;
    }

    op[j]           = make_float4(o0[0], o0[1], o0[2], o0[3]);
    op[j + HW4]     = make_float4(o1[0], o1[1], o1[2], o1[3]);
    op[j + 2 * HW4] = make_float4(o2[0], o2[1], o2[2], o2[3]);
}

extern "C" void kernel_launch(void* const* d_in, const int* in_sizes, int n_in,
                              void* d_out, int out_size) {
    const float* x   = (const float*)d_in[0];   // (4,3,1080,1920) fp32
    const float* LUT = (const float*)d_in[1];   // (3,33,33,33) fp32
    float* out = (float*)d_out;

    pack_lut_kernel<<<(NPAIR + 255) / 256, 256>>>(LUT);

    int total = NBATCH * HW4;                   // 2,073,600 threads
    lut_apply_kernel<<<(total + 255) / 256, 256>>>(x, out);
}

// round 3
// speedup vs baseline: 2.0839x; 1.3287x over previous
#include <cuda_runtime.h>
#include <cuda_fp16.h>
#include <stdint.h>

#define LUT_DIM 33
#define CH_STRIDE (33 * 33 * 33)      // per-channel stride in source LUT (floats)
#define NBLK (33 * 32 * 32)           // superblocks: b in [0,33), g in [0,32), r in [0,32)
#define HW (1080 * 1920)              // pixels per plane
#define HW4 (HW / 4)                  // float4 groups per plane
#define NBATCH 4

// Superblock LUT: for each (b, g, r), a 32-byte block holding the 4 bilinear
// corners of the (g,r) patch at that b, each as fp16 {c0, c1, c2, pad} (8B):
//   [ e(g,r) | e(g,r+1) | e(g+1,r) | e(g+1,r+1) ]
// One LDG.256 per (db) -> 2 divergent gathers per pixel total.
__device__ __align__(32) unsigned int g_blocks[NBLK * 8];

__device__ __forceinline__ unsigned int pack_c01(const float* LUT, int idx) {
    __half2 h = __floats2half2_rn(LUT[idx], LUT[idx + CH_STRIDE]);
    return *reinterpret_cast<unsigned int*>(&h);
}
__device__ __forceinline__ unsigned int pack_c2(const float* LUT, int idx) {
    __half2 h = __floats2half2_rn(LUT[idx + 2 * CH_STRIDE], 0.0f);
    return *reinterpret_cast<unsigned int*>(&h);
}

__global__ void pack_lut_kernel(const float* __restrict__ LUT) {
    int i = blockIdx.x * blockDim.x + threadIdx.x;
    if (i >= NBLK) return;
    int r = i & 31;
    int g = (i >> 5) & 31;
    int b = i >> 10;
    // source index of (b, g, r) in one channel plane
    int base = (b * 33 + g) * 33 + r;
    unsigned int blk[8];
    // e(g, r)
    blk[0] = pack_c01(LUT, base);
    blk[1] = pack_c2 (LUT, base);
    // e(g, r+1)
    blk[2] = pack_c01(LUT, base + 1);
    blk[3] = pack_c2 (LUT, base + 1);
    // e(g+1, r)
    blk[4] = pack_c01(LUT, base + 33);
    blk[5] = pack_c2 (LUT, base + 33);
    // e(g+1, r+1)
    blk[6] = pack_c01(LUT, base + 33 + 1);
    blk[7] = pack_c2 (LUT, base + 33 + 1);
#pragma unroll
    for (int k = 0; k < 8; k++) g_blocks[i * 8 + k] = blk[k];
}

struct F3 { float x, y, z; };

__device__ __forceinline__ float2 h2f(unsigned int u) {
    __half2 h = *reinterpret_cast<__half2*>(&u);
    return __half22float2(h);
}

// Weighted sum of the 4 corners in one superblock (weights w00,w01,w10,w11
// correspond to e(g,r), e(g,r+1), e(g+1,r), e(g+1,r+1)).
__device__ __forceinline__ F3 bilerp_block(const unsigned int v[8],
                                           float w00, float w01, float w10, float w11) {
    float2 a01 = h2f(v[0]); float a2 = h2f(v[1]).x;   // e(g,r)
    float2 b01 = h2f(v[2]); float b2 = h2f(v[3]).x;   // e(g,r+1)
    float2 c01 = h2f(v[4]); float c2 = h2f(v[5]).x;   // e(g+1,r)
    float2 d01 = h2f(v[6]); float d2 = h2f(v[7]).x;   // e(g+1,r+1)
    F3 o;
    o.x = fmaf(w00, a01.x, fmaf(w01, b01.x, fmaf(w10, c01.x, w11 * d01.x)));
    o.y = fmaf(w00, a01.y, fmaf(w01, b01.y, fmaf(w10, c01.y, w11 * d01.y)));
    o.z = fmaf(w00, a2,    fmaf(w01, b2,    fmaf(w10, c2,    w11 * d2)));
    return o;
}

__device__ __forceinline__ void ldg256(const unsigned int* p, unsigned int v[8]) {
    asm volatile("ld.global.v8.b32 {%0,%1,%2,%3,%4,%5,%6,%7}, [%8];"
                 : "=r"(v[0]), "=r"(v[1]), "=r"(v[2]), "=r"(v[3]),
                   "=r"(v[4]), "=r"(v[5]), "=r"(v[6]), "=r"(v[7])
                 : "l"(p));
}

__device__ __forceinline__ F3 lut_interp(float r, float g, float b) {
    float sr = __saturatef(r) * 32.0f;
    float sg = __saturatef(g) * 32.0f;
    float sb = __saturatef(b) * 32.0f;
    int ri = min((int)sr, 31);
    int gi = min((int)sg, 31);
    int bi = min((int)sb, 31);
    float fr = sr - (float)ri;
    float fg = sg - (float)gi;
    float fb = sb - (float)bi;

    // superblock index: ((b*32 + g)*32 + r), in units of 8 u32
    int q = (((bi << 5) + gi) << 5) + ri;
    const int DB = 32 * 32;   // +1 in b

    unsigned int v0[8], v1[8];
    ldg256(g_blocks + (size_t)q * 8, v0);
    ldg256(g_blocks + (size_t)(q + DB) * 8, v1);

    float wr1 = fr, wr0 = 1.0f - fr;
    float wg1 = fg, wg0 = 1.0f - fg;
    float w00 = wg0 * wr0, w01 = wg0 * wr1, w10 = wg1 * wr0, w11 = wg1 * wr1;

    F3 lo = bilerp_block(v0, w00, w01, w10, w11);
    F3 hi = bilerp_block(v1, w00, w01, w10, w11);

    F3 o = { fmaf(fb, hi.x - lo.x, lo.x),
             fmaf(fb, hi.y - lo.y, lo.y),
             fmaf(fb, hi.z - lo.z, lo.z) };
    return o;
}

__global__ void __launch_bounds__(256)
lut_apply_kernel(const float* __restrict__ x, float* __restrict__ out) {
    int tid = blockIdx.x * blockDim.x + threadIdx.x;
    if (tid >= NBATCH * HW4) return;
    int b = tid / HW4;
    int j = tid - b * HW4;

    const float4* xp = reinterpret_cast<const float4*>(x) + (size_t)b * 3 * HW4;
    float4* op = reinterpret_cast<float4*>(out) + (size_t)b * 3 * HW4;

    float4 r4 = __ldg(xp + j);
    float4 g4 = __ldg(xp + j + HW4);
    float4 b4 = __ldg(xp + j + 2 * HW4);

    float rs[4] = { r4.x, r4.y, r4.z, r4.w };
    float gs[4] = { g4.x, g4.y, g4.z, g4.w };
    float bs[4] = { b4.x, b4.y, b4.z, b4.w };
    float o0[4], o1[4], o2[4];

#pragma unroll
    for (int i = 0; i < 4; i++) {
        F3 v = lut_interp(rs[i], gs[i], bs[i]);
        o0[i] = v.x; o1[i] = v.y; o2[i] = v.z;
    }

    op[j]           = make_float4(o0[0], o0[1], o0[2], o0[3]);
    op[j + HW4]     = make_float4(o1[0], o1[1], o1[2], o1[3]);
    op[j + 2 * HW4] = make_float4(o2[0], o2[1], o2[2], o2[3]);
}

extern "C" void kernel_launch(void* const* d_in, const int* in_sizes, int n_in,
                              void* d_out, int out_size) {
    const float* x   = (const float*)d_in[0];   // (4,3,1080,1920) fp32
    const float* LUT = (const float*)d_in[1];   // (3,33,33,33) fp32
    float* out = (float*)d_out;

    pack_lut_kernel<<<(NBLK + 255) / 256, 256>>>(LUT);

    int total = NBATCH * HW4;                   // 2,073,600 threads
    lut_apply_kernel<<<(total + 255) / 256, 256>>>(x, out);
}

// round 4
// speedup vs baseline: 2.5168x; 1.2078x over previous
#include <cuda_runtime.h>
#include <cuda_fp16.h>
#include <stdint.h>

#define LUT_N 35937                   // 33^3 entries per channel
#define CH_STRIDE 35937
#define HW (1080 * 1920)
#define HW4 (HW / 4)
#define NBATCH 4
#define NV (NBATCH * HW4)             // 2,073,600 float4 groups
#define NBLOCKS 152                   // one persistent CTA per SM (GB300: 152 SMs)
#define NTHREADS 1024
// SMEM: c01 table (half2 per entry, 4B) + c2 table (half per entry, 2B)
#define SMEM_BYTES (LUT_N * 4 + LUT_N * 2)   // 215,622 bytes

struct F3 { float x, y, z; };

__device__ __forceinline__ float2 h2f(unsigned int u) {
    __half2 h = *reinterpret_cast<__half2*>(&u);
    return __half22float2(h);
}
__device__ __forceinline__ float2 lerp2(float2 a, float2 b, float f) {
    return make_float2(fmaf(f, b.x - a.x, a.x), fmaf(f, b.y - a.y, a.y));
}

__global__ void __launch_bounds__(NTHREADS, 1)
lut_apply_smem(const float* __restrict__ x, const float* __restrict__ LUT,
               float* __restrict__ out) {
    extern __shared__ unsigned char smem[];
    unsigned int* c01 = reinterpret_cast<unsigned int*>(smem);          // half2 {c0,c1}
    __half*       c2  = reinterpret_cast<__half*>(smem + LUT_N * 4);    // {c2}

    // ── Fill SMEM LUT (fp32 -> fp16), all CTAs read the same L2-resident LUT ──
    for (int i = threadIdx.x; i < LUT_N; i += NTHREADS) {
        float l0 = LUT[i];
        float l1 = LUT[i + CH_STRIDE];
        float l2 = LUT[i + 2 * CH_STRIDE];
        __half2 h = __floats2half2_rn(l0, l1);
        c01[i] = *reinterpret_cast<unsigned int*>(&h);
        c2[i]  = __float2half_rn(l2);
    }
    __syncthreads();

    // ── Persistent grid-stride over float4 pixel groups ──
    for (int v = blockIdx.x * NTHREADS + threadIdx.x; v < NV;
         v += NBLOCKS * NTHREADS) {
        int b = v / HW4;
        int j = v - b * HW4;

        const float4* xp = reinterpret_cast<const float4*>(x) + (size_t)b * 3 * HW4;
        float4*       op = reinterpret_cast<float4*>(out)     + (size_t)b * 3 * HW4;

        float4 r4 = xp[j];
        float4 g4 = xp[j + HW4];
        float4 b4 = xp[j + 2 * HW4];

        float rs[4] = { r4.x, r4.y, r4.z, r4.w };
        float gs[4] = { g4.x, g4.y, g4.z, g4.w };
        float bs[4] = { b4.x, b4.y, b4.z, b4.w };
        float o0[4], o1[4], o2[4];

#pragma unroll
        for (int i = 0; i < 4; i++) {
            float sr = __saturatef(rs[i]) * 32.0f;
            float sg = __saturatef(gs[i]) * 32.0f;
            float sb = __saturatef(bs[i]) * 32.0f;
            int ri = min((int)sr, 31);
            int gi = min((int)sg, 31);
            int bi = min((int)sb, 31);
            float fr = sr - (float)ri;
            float fg = sg - (float)gi;
            float fb = sb - (float)bi;

            int q = (bi * 33 + gi) * 33 + ri;   // corner (b,g,r); +1:r, +33:g, +1089:b

            // 8 corners: channels 0,1 packed (LDS.32)
            unsigned int a000 = c01[q];            unsigned int a001 = c01[q + 1];
            unsigned int a010 = c01[q + 33];       unsigned int a011 = c01[q + 34];
            unsigned int a100 = c01[q + 1089];     unsigned int a101 = c01[q + 1090];
            unsigned int a110 = c01[q + 1122];     unsigned int a111 = c01[q + 1123];
            // channel 2 (LDS.16)
            float z000 = __half2float(c2[q]);          float z001 = __half2float(c2[q + 1]);
            float z010 = __half2float(c2[q + 33]);     float z011 = __half2float(c2[q + 34]);
            float z100 = __half2float(c2[q + 1089]);   float z101 = __half2float(c2[q + 1090]);
            float z110 = __half2float(c2[q + 1122]);   float z111 = __half2float(c2[q + 1123]);

            // trilinear cascade, channels 0&1 as float2
            float2 e00 = lerp2(h2f(a000), h2f(a001), fr);
            float2 e01 = lerp2(h2f(a010), h2f(a011), fr);
            float2 e10 = lerp2(h2f(a100), h2f(a101), fr);
            float2 e11 = lerp2(h2f(a110), h2f(a111), fr);
            float2 eg0 = lerp2(e00, e01, fg);
            float2 eg1 = lerp2(e10, e11, fg);
            float2 ec  = lerp2(eg0, eg1, fb);

            // channel 2 scalar cascade
            float s00 = fmaf(fr, z001 - z000, z000);
            float s01 = fmaf(fr, z011 - z010, z010);
            float s10 = fmaf(fr, z101 - z100, z100);
            float s11 = fmaf(fr, z111 - z110, z110);
            float sg0 = fmaf(fg, s01 - s00, s00);
            float sg1 = fmaf(fg, s11 - s10, s10);
            float sc  = fmaf(fb, sg1 - sg0, sg0);

            o0[i] = ec.x; o1[i] = ec.y; o2[i] = sc;
        }

        op[j]           = make_float4(o0[0], o0[1], o0[2], o0[3]);
        op[j + HW4]     = make_float4(o1[0], o1[1], o1[2], o1[3]);
        op[j + 2 * HW4] = make_float4(o2[0], o2[1], o2[2], o2[3]);
    }
}

extern "C" void kernel_launch(void* const* d_in, const int* in_sizes, int n_in,
                              void* d_out, int out_size) {
    const float* x   = (const float*)d_in[0];   // (4,3,1080,1920) fp32
    const float* LUT = (const float*)d_in[1];   // (3,33,33,33) fp32
    float* out = (float*)d_out;

    // Opt into >48KB dynamic SMEM once (first call is the pre-capture
    // correctness run; the attribute persists for the captured graph).
    static bool smem_ok = []() {
        cudaFuncSetAttribute(lut_apply_smem,
                             cudaFuncAttributeMaxDynamicSharedMemorySize,
                             SMEM_BYTES);
        return true;
    }();
    (void)smem_ok;

    lut_apply_smem<<<NBLOCKS, NTHREADS, SMEM_BYTES>>>(x, LUT, out);
}